// round 5
// baseline (speedup 1.0000x reference)
#include <cuda_runtime.h>
#include <math.h>
#include <limits.h>

// Fixed problem shape (setup_inputs): B=8, P=512, Q=4096, H=W=512
#define B_   8
#define P_   512
#define Q_   4096
#define N_   4096
#define R_   45
#define HW_  512

#define THREADS_   512
#define PTS_BLOCKS 256   // 16 query-warps per block; 32 blocks per batch
#define CE_BLOCKS  32    // 1024 queries per block (2 per thread)
#define TOTAL_BLOCKS (PTS_BLOCKS + CE_BLOCKS)

__device__ float        g_pts_part[PTS_BLOCKS];
__device__ float        g_ce_num[CE_BLOCKS];
__device__ float        g_ce_den[CE_BLOCKS];
__device__ unsigned int g_done;          // 0 at load; final block self-resets

__device__ __forceinline__ float softplusf(float d) {
    return fmaxf(d, 0.f) + log1pf(expf(-fabsf(d)));
}

__device__ __forceinline__ float warp_sum(float v) {
    #pragma unroll
    for (int o = 16; o; o >>= 1) v += __shfl_xor_sync(0xffffffffu, v, o);
    return v;
}

__global__ void __launch_bounds__(THREADS_) k_fused(
    const float* __restrict__ tp,
    const float* __restrict__ sp,
    const float* __restrict__ logits,
    const int*   __restrict__ sidx,
    float* __restrict__ out)
{
    __shared__ int      s_pts[P_];        // packed px | py<<16
    __shared__ float    sm[32];
    __shared__ float    sm2[32];
    __shared__ unsigned bm[Q_ / 32];
    __shared__ int      s_last;

    const int tid  = threadIdx.x;
    const int bid  = blockIdx.x;
    const int warp = tid >> 5, lane = tid & 31;

    if (bid < PTS_BLOCKS) {
        // ============ points focal loss: 16 query-warps per block ============
        const int b = bid >> 5;                     // 32 blocks per batch

        // each thread packs one point (float2 load)
        {
            float2 v = ((const float2*)(tp + (size_t)b * P_ * 2))[tid];
            int px = min(max((int)rintf(v.x), 0), HW_ - 1);
            int py = min(max((int)rintf(v.y), 0), HW_ - 1);
            s_pts[tid] = px | (py << 16);
        }

        // query setup BEFORE the barrier (overlaps the tp DRAM latency)
        const int q = bid * 16 + warp;
        float x = fminf(fmaxf(sp[2 * q]     * (float)HW_, 0.f), (float)(HW_ - 1));
        float y = fminf(fmaxf(sp[2 * q + 1] * (float)HW_, 0.f), (float)(HW_ - 1));
        float x0f = floorf(x), y0f = floorf(y);
        int x0 = (int)x0f, y0 = (int)y0f;
        float wx = x - x0f, wy = y - y0f;
        __syncthreads();

        int m00 = INT_MAX, m01 = INT_MAX, m10 = INT_MAX, m11 = INT_MAX;
        const int4* pts4 = (const int4*)s_pts;      // 128 int4
        #pragma unroll
        for (int i = 0; i < 4; i++) {
            int4 w4 = pts4[i * 32 + lane];
            #pragma unroll
            for (int k = 0; k < 4; k++) {
                int w  = (k == 0) ? w4.x : (k == 1) ? w4.y : (k == 2) ? w4.z : w4.w;
                int px = w & 0xFFFF, py = w >> 16;
                int dx0 = x0 - px,  dy0 = y0 - py;
                int ax  = dx0 + R_, ay  = dy0 + R_;
                bool cx0 = (unsigned)ax       <= 2u * R_;
                bool cx1 = (unsigned)(ax + 1) <= 2u * R_;
                bool cy0 = (unsigned)ay       <= 2u * R_;
                bool cy1 = (unsigned)(ay + 1) <= 2u * R_;
                int a0 = dx0 * dx0;
                int a1 = (dx0 + 1) * (dx0 + 1);
                int e0 = dy0 * dy0;
                int e1 = (dy0 + 1) * (dy0 + 1);
                if (cx0 && cy0) m00 = min(m00, a0 + e0);
                if (cx1 && cy0) m01 = min(m01, a1 + e0);
                if (cx0 && cy1) m10 = min(m10, a0 + e1);
                if (cx1 && cy1) m11 = min(m11, a1 + e1);
            }
        }
        m00 = (int)__reduce_min_sync(0xffffffffu, (unsigned)m00);
        m01 = (int)__reduce_min_sync(0xffffffffu, (unsigned)m01);
        m10 = (int)__reduce_min_sync(0xffffffffu, (unsigned)m10);
        m11 = (int)__reduce_min_sync(0xffffffffu, (unsigned)m11);

        if (lane == 0) {
            const float inv = 1.0f / (2.0f * 15.0f * 15.0f);
            float v00 = (m00 == INT_MAX) ? 0.f : expf(-(float)m00 * inv);
            float v01 = (m01 == INT_MAX) ? 0.f : expf(-(float)m01 * inv);
            float v10 = (m10 == INT_MAX) ? 0.f : expf(-(float)m10 * inv);
            float v11 = (m11 == INT_MAX) ? 0.f : expf(-(float)m11 * inv);
            float p = v00 * (1.f - wx) * (1.f - wy) + v01 * wx * (1.f - wy)
                    + v10 * (1.f - wx) * wy         + v11 * wx * wy;
            float om = 1.f - p;
            sm[warp] = -om * om * logf(fmaxf(p, 1e-6f));
        }
        __syncthreads();
        if (warp == 0) {
            float v = (lane < 16) ? sm[lane] : 0.f;
            v = warp_sum(v);
            if (lane == 0) g_pts_part[bid] = v;
        }
    } else {
        // ====== CE: weighted cross-entropy, 1024 queries per block ======
        const int cb = bid - PTS_BLOCKS;
        const int b  = cb >> 2;          // batch
        const int s  = cb & 3;           // quarter of Q

        if (tid < Q_ / 32) bm[tid] = 0u;
        __syncthreads();
        {
            int i0 = sidx[b * P_ + tid];
            atomicOr(&bm[i0 >> 5], 1u << (i0 & 31));
        }
        __syncthreads();

        // one float4 per thread == 2 (q, logit-pair) elements
        float4 l = ((const float4*)(logits + (size_t)b * Q_ * 2 + s * 2048))[tid];
        int q0 = s * 1024 + 2 * tid, q1 = q0 + 1;
        bool f0 = (bm[q0 >> 5] >> (q0 & 31)) & 1u;
        bool f1 = (bm[q1 >> 5] >> (q1 & 31)) & 1u;
        float d0 = l.y - l.x, d1 = l.w - l.z;
        float num = (f0 ? softplusf(-d0) : 0.5f * softplusf(d0))
                  + (f1 ? softplusf(-d1) : 0.5f * softplusf(d1));
        float den = (f0 ? 1.f : 0.5f) + (f1 ? 1.f : 0.5f);

        num = warp_sum(num);
        den = warp_sum(den);
        if (lane == 0) { sm[warp] = num; sm2[warp] = den; }
        __syncthreads();
        if (warp == 0) {
            float n = (lane < 16) ? sm[lane]  : 0.f;
            float d = (lane < 16) ? sm2[lane] : 0.f;
            n = warp_sum(n);
            d = warp_sum(d);
            if (lane == 0) { g_ce_num[cb] = n; g_ce_den[cb] = d; }
        }
    }

    // ---------------- last-block-done finalize ----------------
    __syncthreads();
    if (tid == 0) {
        __threadfence();
        unsigned int prev = atomicAdd(&g_done, 1u);
        s_last = (prev == (unsigned)(TOTAL_BLOCKS - 1)) ? 1 : 0;
    }
    __syncthreads();
    if (s_last) {
        __threadfence();
        volatile float* pp = g_pts_part;
        volatile float* cn = g_ce_num;
        volatile float* cd = g_ce_den;

        // pts partials: first 256 threads hold one each
        float v = (tid < PTS_BLOCKS) ? pp[tid] : 0.f;
        v = warp_sum(v);
        if (lane == 0) sm[warp] = v;
        __syncthreads();
        if (warp == 0) {
            float pv = (lane < 16) ? sm[lane] : 0.f;
            pv = warp_sum(pv);                         // ptsSum on lane 0
            float n = (lane < CE_BLOCKS) ? cn[lane] : 0.f;
            float d = (lane < CE_BLOCKS) ? cd[lane] : 0.f;
            n = warp_sum(n);
            d = warp_sum(d);
            if (lane == 0) {
                out[0] = n / d + 0.5f * pv / (float)N_;
                g_done = 0u;                           // reset for graph replay
            }
        }
    }
}

extern "C" void kernel_launch(void* const* d_in, const int* in_sizes, int n_in,
                              void* d_out, int out_size) {
    const float* tp     = (const float*)d_in[0];
    const float* sp     = (const float*)d_in[1];
    const float* logits = (const float*)d_in[2];
    const int*   sidx   = (const int*)  d_in[4];

    k_fused<<<TOTAL_BLOCKS, THREADS_>>>(tp, sp, logits, sidx, (float*)d_out);
}

// round 6
// speedup vs baseline: 1.2657x; 1.2657x over previous
#include <cuda_runtime.h>
#include <math.h>
#include <limits.h>

// Fixed problem shape (setup_inputs): B=8, P=512, Q=4096, H=W=512
#define B_   8
#define P_   512
#define Q_   4096
#define N_   4096
#define R_   45
#define HW_  512

#define THREADS_   256
#define PTS_BLOCKS 512   // 8 query-warps/block; 64 blocks per batch
#define CE_BLOCKS  64    // 512 queries per block (2 per thread)
#define TOTAL_BLOCKS (PTS_BLOCKS + CE_BLOCKS)

__device__ float        g_pts_part[PTS_BLOCKS];
__device__ float        g_ce_num[CE_BLOCKS];
__device__ float        g_ce_den[CE_BLOCKS];
__device__ unsigned int g_done;          // 0 at load; final block self-resets

__device__ __forceinline__ float softplusf(float d) {
    return fmaxf(d, 0.f) + log1pf(expf(-fabsf(d)));
}

__device__ __forceinline__ float warp_sum(float v) {
    #pragma unroll
    for (int o = 16; o; o >>= 1) v += __shfl_xor_sync(0xffffffffu, v, o);
    return v;
}

__global__ void __launch_bounds__(THREADS_) k_fused(
    const float* __restrict__ tp,
    const float* __restrict__ sp,
    const float* __restrict__ logits,
    const int*   __restrict__ sidx,
    float* __restrict__ out)
{
    __shared__ int      s_pts[P_];        // cell-sorted, packed px | py<<16
    __shared__ int      s_cnt[64];
    __shared__ int      s_off[65];
    __shared__ float    sm[32], sm2[32], sm3[32];
    __shared__ unsigned bm[Q_ / 32];      // 128 words (CE branch)
    __shared__ int      s_last;

    const int tid  = threadIdx.x;
    const int bid  = blockIdx.x;
    const int warp = tid >> 5, lane = tid & 31;

    if (bid < PTS_BLOCKS) {
        // ========== points focal loss: 2D counting sort + cell-range scan ==========
        const int b = bid >> 6;                       // 64 blocks per batch
        const int q = bid * 8 + warp;

        // query coords first (independent LDG, overlaps everything below)
        float2 sq = ((const float2*)sp)[q];
        float x = fminf(fmaxf(sq.x * (float)HW_, 0.f), (float)(HW_ - 1));
        float y = fminf(fmaxf(sq.y * (float)HW_, 0.f), (float)(HW_ - 1));
        float x0f = floorf(x), y0f = floorf(y);
        int x0 = (int)x0f, y0 = (int)y0f;
        float wx = x - x0f, wy = y - y0f;

        if (tid < 64) s_cnt[tid] = 0;
        __syncthreads();

        // each thread owns two points (one float4)
        int pkA, pkB, cA, cB, rA, rB;
        {
            float4 v = ((const float4*)(tp + (size_t)b * P_ * 2))[tid];
            int pxa = min(max((int)rintf(v.x), 0), HW_ - 1);
            int pya = min(max((int)rintf(v.y), 0), HW_ - 1);
            int pxb = min(max((int)rintf(v.z), 0), HW_ - 1);
            int pyb = min(max((int)rintf(v.w), 0), HW_ - 1);
            pkA = pxa | (pya << 16);  cA = ((pya >> 6) << 3) | (pxa >> 6);
            pkB = pxb | (pyb << 16);  cB = ((pyb >> 6) << 3) | (pxb >> 6);
            rA = atomicAdd(&s_cnt[cA], 1);
            rB = atomicAdd(&s_cnt[cB], 1);
        }
        __syncthreads();
        if (warp == 0) {                              // 64-cell exclusive scan
            int c0 = s_cnt[lane], c1 = s_cnt[lane + 32];
            int i0 = c0, i1 = c1;
            #pragma unroll
            for (int o = 1; o < 32; o <<= 1) {
                int t = __shfl_up_sync(0xffffffffu, i0, o); if (lane >= o) i0 += t;
                int u = __shfl_up_sync(0xffffffffu, i1, o); if (lane >= o) i1 += u;
            }
            int tot0 = __shfl_sync(0xffffffffu, i0, 31);
            i1 += tot0;
            s_off[lane + 1]  = i0;                    // exclusive: off[k+1] = incl[k]
            s_off[lane + 33] = i1;
            if (lane == 0) s_off[0] = 0;
        }
        __syncthreads();
        s_pts[s_off[cA] + rA] = pkA;
        s_pts[s_off[cB] + rB] = pkB;
        __syncthreads();

        // cells overlapping [x0-45, x0+46] x [y0-45, y0+46]
        int cxlo = max(x0 - R_, 0) >> 6;
        int cxhi = min(x0 + R_ + 1, HW_ - 1) >> 6;
        int cylo = max(y0 - R_, 0) >> 6;
        int cyhi = min(y0 + R_ + 1, HW_ - 1) >> 6;

        int m00 = INT_MAX, m01 = INT_MAX, m10 = INT_MAX, m11 = INT_MAX;
        for (int cy = cylo; cy <= cyhi; cy++) {       // 2-3 rows
            int j0 = s_off[(cy << 3) | cxlo];
            int j1 = s_off[(cy << 3) + cxhi + 1];     // contiguous run in row
            for (int j = j0 + lane; j < j1; j += 32) {
                int w  = s_pts[j];
                int px = w & 0xFFFF, py = w >> 16;
                int dx0 = x0 - px, dy0 = y0 - py;
                bool cx0 = (unsigned)(dx0 + R_)     <= 2u * R_;
                bool cx1 = (unsigned)(dx0 + R_ + 1) <= 2u * R_;
                bool cy0 = (unsigned)(dy0 + R_)     <= 2u * R_;
                bool cy1 = (unsigned)(dy0 + R_ + 1) <= 2u * R_;
                int a0 = dx0 * dx0, e0 = dy0 * dy0;
                int k00 = a0 + e0;
                int k01 = k00 + 2 * dx0 + 1;
                int k10 = k00 + 2 * dy0 + 1;
                int k11 = k01 + 2 * dy0 + 1;
                if (cx0 && cy0) m00 = min(m00, k00);
                if (cx1 && cy0) m01 = min(m01, k01);
                if (cx0 && cy1) m10 = min(m10, k10);
                if (cx1 && cy1) m11 = min(m11, k11);
            }
        }
        m00 = (int)__reduce_min_sync(0xffffffffu, (unsigned)m00);
        m01 = (int)__reduce_min_sync(0xffffffffu, (unsigned)m01);
        m10 = (int)__reduce_min_sync(0xffffffffu, (unsigned)m10);
        m11 = (int)__reduce_min_sync(0xffffffffu, (unsigned)m11);

        if (lane == 0) {
            const float inv = 1.0f / (2.0f * 15.0f * 15.0f);
            float v00 = (m00 == INT_MAX) ? 0.f : expf(-(float)m00 * inv);
            float v01 = (m01 == INT_MAX) ? 0.f : expf(-(float)m01 * inv);
            float v10 = (m10 == INT_MAX) ? 0.f : expf(-(float)m10 * inv);
            float v11 = (m11 == INT_MAX) ? 0.f : expf(-(float)m11 * inv);
            float p = v00 * (1.f - wx) * (1.f - wy) + v01 * wx * (1.f - wy)
                    + v10 * (1.f - wx) * wy         + v11 * wx * wy;
            float om = 1.f - p;
            sm[warp] = -om * om * logf(fmaxf(p, 1e-6f));
        }
        __syncthreads();
        if (warp == 0) {
            float v = (lane < 8) ? sm[lane] : 0.f;
            v = warp_sum(v);
            if (lane == 0) g_pts_part[bid] = v;
        }
    } else {
        // ====== CE: weighted cross-entropy, one block per 512-query slice ======
        const int cb = bid - PTS_BLOCKS;
        const int b  = cb >> 3;          // batch
        const int s  = cb & 7;           // slice

        // hoist both global loads (independent) before any barrier
        float4 l = ((const float4*)(logits + (size_t)b * Q_ * 2 + s * 1024))[tid];
        int i0 = sidx[b * P_ + tid];
        int i1 = sidx[b * P_ + 256 + tid];

        if (tid < Q_ / 32) bm[tid] = 0u;
        __syncthreads();
        atomicOr(&bm[i0 >> 5], 1u << (i0 & 31));
        atomicOr(&bm[i1 >> 5], 1u << (i1 & 31));
        __syncthreads();

        int q0 = s * 512 + 2 * tid, q1 = q0 + 1;
        bool f0 = (bm[q0 >> 5] >> (q0 & 31)) & 1u;
        bool f1 = (bm[q1 >> 5] >> (q1 & 31)) & 1u;
        float d0 = l.y - l.x, d1 = l.w - l.z;
        float num = (f0 ? softplusf(-d0) : 0.5f * softplusf(d0))
                  + (f1 ? softplusf(-d1) : 0.5f * softplusf(d1));
        float den = (f0 ? 1.f : 0.5f) + (f1 ? 1.f : 0.5f);

        num = warp_sum(num);
        den = warp_sum(den);
        if (lane == 0) { sm[warp] = num; sm2[warp] = den; }
        __syncthreads();
        if (warp == 0) {
            float n = (lane < 8) ? sm[lane]  : 0.f;
            float d = (lane < 8) ? sm2[lane] : 0.f;
            n = warp_sum(n);
            d = warp_sum(d);
            if (lane == 0) { g_ce_num[cb] = n; g_ce_den[cb] = d; }
        }
    }

    // ---------------- last-block-done finalize ----------------
    __syncthreads();
    if (tid == 0) {
        __threadfence();
        unsigned int prev = atomicAdd(&g_done, 1u);
        s_last = (prev == (unsigned)(TOTAL_BLOCKS - 1)) ? 1 : 0;
    }
    __syncthreads();
    if (s_last) {
        __threadfence();
        volatile float* pp = g_pts_part;
        volatile float* cn = g_ce_num;
        volatile float* cd = g_ce_den;

        float v = pp[tid] + pp[tid + 256];
        float n = (tid < CE_BLOCKS) ? cn[tid] : 0.f;
        float d = (tid < CE_BLOCKS) ? cd[tid] : 0.f;
        v = warp_sum(v);
        n = warp_sum(n);
        d = warp_sum(d);
        if (lane == 0) { sm[warp] = v; sm2[warp] = n; sm3[warp] = d; }
        __syncthreads();
        if (tid == 0) {
            float pv = 0.f, nn = 0.f, dd = 0.f;
            #pragma unroll
            for (int k = 0; k < 8; k++) { pv += sm[k]; nn += sm2[k]; dd += sm3[k]; }
            out[0] = nn / dd + 0.5f * pv / (float)N_;
            g_done = 0u;                               // reset for graph replay
        }
    }
}

extern "C" void kernel_launch(void* const* d_in, const int* in_sizes, int n_in,
                              void* d_out, int out_size) {
    const float* tp     = (const float*)d_in[0];
    const float* sp     = (const float*)d_in[1];
    const float* logits = (const float*)d_in[2];
    const int*   sidx   = (const int*)  d_in[4];

    k_fused<<<TOTAL_BLOCKS, THREADS_>>>(tp, sp, logits, sidx, (float*)d_out);
}